// round 2
// baseline (speedup 1.0000x reference)
#include <cuda_runtime.h>
#include <cuda_bf16.h>

#define NN 4096
#define FD 128
#define MAXNBR 128

// Scratch (device globals; no cudaMalloc allowed)
__device__ float          g_S[(size_t)NN * NN];        // 64 MB: S = exp(f^T C f)
__device__ unsigned short g_idx[(size_t)NN * MAXNBR];  // packed neighbor cols
__device__ int            g_cnt[NN];

// ---------------------------------------------------------------------------
// Kernel 0: build ordered neighbor lists via warp ballot (deterministic)
// One warp per adjacency row.
// ---------------------------------------------------------------------------
__global__ void build_nbr_kernel(const float* __restrict__ nbr) {
    const int warp = threadIdx.x >> 5;
    const int lane = threadIdx.x & 31;
    const int j = blockIdx.x * 8 + warp;
    const float* row = nbr + (size_t)j * NN;
    unsigned short* lst = g_idx + (size_t)j * MAXNBR;

    int base = 0;
    #pragma unroll 4
    for (int step = 0; step < NN / 32; ++step) {
        int col = step * 32 + lane;
        bool hit = (row[col] != 0.0f);
        unsigned mask = __ballot_sync(0xFFFFFFFFu, hit);
        if (hit) {
            int pos = base + __popc(mask & ((1u << lane) - 1u));
            if (pos < MAXNBR) lst[pos] = (unsigned short)col;
        }
        base += __popc(mask);
    }
    if (lane == 0) g_cnt[j] = min(base, MAXNBR);
}

// ---------------------------------------------------------------------------
// Kernel 1: S = exp(f^T diag(wq*wk) f)  — symmetric, upper-tri tiles + mirror
// 64x64 tile per CTA, 256 threads, 4x4 per thread, K=128 in two 64-chunks.
// ---------------------------------------------------------------------------
__global__ void compute_S_kernel(const float* __restrict__ f,
                                 const float* __restrict__ wq,
                                 const float* __restrict__ wk) {
    const int ti = blockIdx.y;
    const int tj = blockIdx.x;
    if (tj < ti) return;  // upper triangle only (mirror written below)

    __shared__ float smem[2 * 64 * 64];   // As | Bs  (32 KB)
    __shared__ float cs[FD];
    float* As = smem;            // As[d2*64 + i_local] = c[d]*f[d][i0+i_local]
    float* Bs = smem + 64 * 64;  // Bs[d2*64 + j_local] = f[d][j0+j_local]

    const int tid = threadIdx.x;          // 0..255
    const int tx = tid & 15;
    const int ty = tid >> 4;
    const int i0 = ti * 64;
    const int j0 = tj * 64;

    if (tid < FD) cs[tid] = wq[tid] * wk[tid];
    __syncthreads();

    float acc[4][4] = {};

    #pragma unroll
    for (int kb = 0; kb < 2; ++kb) {
        #pragma unroll
        for (int r = 0; r < 16; ++r) {
            int e = tid + r * 256;          // 0..4095
            int d2 = e >> 6;
            int c  = e & 63;
            int d  = kb * 64 + d2;
            As[e] = cs[d] * f[(size_t)d * NN + i0 + c];
            Bs[e] = f[(size_t)d * NN + j0 + c];
        }
        __syncthreads();

        #pragma unroll 16
        for (int d2 = 0; d2 < 64; ++d2) {
            float4 a = *(const float4*)&As[d2 * 64 + ty * 4];
            float4 b = *(const float4*)&Bs[d2 * 64 + tx * 4];
            acc[0][0] += a.x * b.x; acc[0][1] += a.x * b.y; acc[0][2] += a.x * b.z; acc[0][3] += a.x * b.w;
            acc[1][0] += a.y * b.x; acc[1][1] += a.y * b.y; acc[1][2] += a.y * b.z; acc[1][3] += a.y * b.w;
            acc[2][0] += a.z * b.x; acc[2][1] += a.z * b.y; acc[2][2] += a.z * b.z; acc[2][3] += a.z * b.w;
            acc[3][0] += a.w * b.x; acc[3][1] += a.w * b.y; acc[3][2] += a.w * b.z; acc[3][3] += a.w * b.w;
        }
        __syncthreads();
    }

    float ev[4][4];
    #pragma unroll
    for (int r = 0; r < 4; ++r)
        #pragma unroll
        for (int c = 0; c < 4; ++c)
            ev[r][c] = __expf(acc[r][c]);

    // primary tile write (coalesced float4)
    #pragma unroll
    for (int r = 0; r < 4; ++r) {
        float4 w = make_float4(ev[r][0], ev[r][1], ev[r][2], ev[r][3]);
        *(float4*)&g_S[(size_t)(i0 + ty * 4 + r) * NN + j0 + tx * 4] = w;
    }

    // mirror tile via smem transpose staging
    if (ti != tj) {
        float* st = smem;
        #pragma unroll
        for (int r = 0; r < 4; ++r)
            #pragma unroll
            for (int c = 0; c < 4; ++c)
                st[(tx * 4 + c) * 68 + (ty * 4 + r)] = ev[r][c];
        __syncthreads();
        #pragma unroll
        for (int r = 0; r < 4; ++r) {
            int jl = ty * 4 + r;
            float4 w = *(const float4*)&st[jl * 68 + tx * 4];
            *(float4*)&g_S[(size_t)(j0 + jl) * NN + i0 + tx * 4] = w;
        }
    }
}

// ---------------------------------------------------------------------------
// Kernel 2 (FUSED): gather + divide + transposed write.
// CTA = (col chunk of 1024, j-block of 32). Thread owns one column c.
//   D[j,c]   = sum_{k in nbr(j)} S[k,c]
//   val[jl]  = S[j,c] / D[j,c]          (= out[c,j] by symmetry of S)
// Then each thread writes out[c, j0..j0+31] as 8 contiguous float4s.
// ---------------------------------------------------------------------------
__global__ void __launch_bounds__(1024, 1)
fused_gather_kernel(float* __restrict__ out) {
    __shared__ unsigned short s_idx[32 * MAXNBR];  // 8 KB
    __shared__ int s_cnt[32];

    const int tid = threadIdx.x;            // 0..1023
    const int j0  = blockIdx.y * 32;
    const int c   = blockIdx.x * 1024 + tid;

    // cooperative load of 32 neighbor lists (contiguous in g_idx)
    #pragma unroll
    for (int e = tid; e < 32 * MAXNBR; e += 1024)
        s_idx[e] = g_idx[(size_t)j0 * MAXNBR + e];
    if (tid < 32) s_cnt[tid] = g_cnt[j0 + tid];
    __syncthreads();

    float val[32];

    #pragma unroll
    for (int jl = 0; jl < 32; ++jl) {
        const int cnt = s_cnt[jl];
        const unsigned short* lst = &s_idx[jl * MAXNBR];

        float a0 = 0.f, a1 = 0.f, a2 = 0.f, a3 = 0.f;
        int k = 0;
        for (; k + 4 <= cnt; k += 4) {
            a0 += g_S[(size_t)lst[k + 0] * NN + c];
            a1 += g_S[(size_t)lst[k + 1] * NN + c];
            a2 += g_S[(size_t)lst[k + 2] * NN + c];
            a3 += g_S[(size_t)lst[k + 3] * NN + c];
        }
        for (; k < cnt; ++k)
            a0 += g_S[(size_t)lst[k] * NN + c];

        float d = (a0 + a1) + (a2 + a3);
        float sj = g_S[(size_t)(j0 + jl) * NN + c];
        val[jl] = sj / d;
    }

    // transposed write: out[c][j0..j0+31] — 128B contiguous per thread
    float4* op = (float4*)(out + (size_t)c * NN + j0);
    #pragma unroll
    for (int q = 0; q < 8; ++q)
        op[q] = make_float4(val[4 * q + 0], val[4 * q + 1],
                            val[4 * q + 2], val[4 * q + 3]);
}

// ---------------------------------------------------------------------------
extern "C" void kernel_launch(void* const* d_in, const int* in_sizes, int n_in,
                              void* d_out, int out_size) {
    const float* f   = (const float*)d_in[0];   // [128, 4096]
    const float* nbr = (const float*)d_in[1];   // [4096, 4096]
    const float* wq  = (const float*)d_in[2];   // [128]
    const float* wk  = (const float*)d_in[3];   // [128]
    float* out = (float*)d_out;                 // [4096, 4096]

    build_nbr_kernel<<<NN / 8, 256>>>(nbr);
    compute_S_kernel<<<dim3(64, 64), 256>>>(f, wq, wk);
    fused_gather_kernel<<<dim3(4, 128), 1024>>>(out);
}

// round 3
// speedup vs baseline: 1.8985x; 1.8985x over previous
#include <cuda_runtime.h>
#include <cuda_fp16.h>

#define NN 4096
#define FD 128
#define MAXNBR 128

// Scratch (device globals; no cudaMalloc allowed)
__device__ float          g_S [(size_t)NN * NN];       // 64 MB fp32 S = exp(f^T C f)
__device__ __half         g_Sh[(size_t)NN * NN];       // 32 MB fp16 copy (for gathers)
__device__ float          g_T [(size_t)NN * NN];       // 64 MB T = out^T
__device__ unsigned short g_idx[(size_t)NN * MAXNBR];
__device__ int            g_cnt[NN];

// fast exp on the FMA pipe (degree-7 Taylor of 2^g on [-0.5,0.5]); rel err ~1e-8
__device__ __forceinline__ float fexp(float x) {
    float t = x * 1.4426950408889634f;
    int   ni = __float2int_rn(t);
    float g = t - (float)ni;
    float p =           1.5252734e-5f;
    p = fmaf(p, g,      1.5403530e-4f);
    p = fmaf(p, g,      1.3333558e-3f);
    p = fmaf(p, g,      9.6181291e-3f);
    p = fmaf(p, g,      5.5504109e-2f);
    p = fmaf(p, g,      2.4022651e-1f);
    p = fmaf(p, g,      6.9314718e-1f);
    p = fmaf(p, g,      1.0f);
    return p * __int_as_float((ni + 127) << 23);
}

// ---------------------------------------------------------------------------
// Kernel 0: ordered neighbor-list build. One warp per row, float4 loads,
// warp-exclusive-scan compaction (deterministic).
// ---------------------------------------------------------------------------
__global__ void build_nbr_kernel(const float* __restrict__ nbr) {
    const int warp = threadIdx.x >> 5;
    const int lane = threadIdx.x & 31;
    const int j = blockIdx.x * 8 + warp;
    const float4* row = (const float4*)(nbr + (size_t)j * NN);
    unsigned short* lst = g_idx + (size_t)j * MAXNBR;

    int base = 0;
    #pragma unroll 4
    for (int step = 0; step < NN / 128; ++step) {       // 32 steps, 128 cols each
        int c4 = step * 32 + lane;                       // float4 index
        float4 v = row[c4];
        int b0 = v.x != 0.0f, b1 = v.y != 0.0f, b2 = v.z != 0.0f, b3 = v.w != 0.0f;
        int cnt4 = b0 + b1 + b2 + b3;
        // inclusive warp scan
        int inc = cnt4;
        #pragma unroll
        for (int s = 1; s < 32; s <<= 1) {
            int o = __shfl_up_sync(0xFFFFFFFFu, inc, s);
            if (lane >= s) inc += o;
        }
        int pos = base + inc - cnt4;
        int col = c4 * 4;
        if (b0 && pos < MAXNBR) lst[pos++] = (unsigned short)(col + 0);
        if (b1 && pos < MAXNBR) lst[pos++] = (unsigned short)(col + 1);
        if (b2 && pos < MAXNBR) lst[pos++] = (unsigned short)(col + 2);
        if (b3 && pos < MAXNBR) lst[pos++] = (unsigned short)(col + 3);
        base += __shfl_sync(0xFFFFFFFFu, inc, 31);
    }
    if (lane == 0) g_cnt[j] = min(base, MAXNBR);
}

// ---------------------------------------------------------------------------
// Kernel 1: S = exp(f^T diag(wq*wk) f), symmetric. 128x128 tile per CTA,
// 256 threads, 8x8 per thread, poly exp, dual fp32+fp16 store, mirror via
// smem-staged chunks.
// ---------------------------------------------------------------------------
__global__ void __launch_bounds__(256, 2)
compute_S_kernel(const float* __restrict__ f,
                 const float* __restrict__ wq,
                 const float* __restrict__ wk) {
    const int ti = blockIdx.y;
    const int tj = blockIdx.x;
    if (tj < ti) return;   // upper triangle (mirror written below)

    __shared__ float s_raw[4224];          // max(As+Bs = 4096, stage 32*132)
    __shared__ float cs[FD];
    float* As = s_raw;                     // As[d2][c] : [16][128]
    float* Bs = s_raw + 16 * 128;          // Bs[d2][c] : [16][128]

    const int tid = threadIdx.x;           // 0..255
    const int tx = tid & 15;
    const int ty = tid >> 4;
    const int i0 = ti * 128;
    const int j0 = tj * 128;

    if (tid < FD) cs[tid] = wq[tid] * wk[tid];
    __syncthreads();

    float acc[8][8] = {};

    #pragma unroll 1
    for (int kb = 0; kb < 8; ++kb) {       // 8 chunks of 16 d-slices
        #pragma unroll
        for (int r = 0; r < 2; ++r) {
            int e  = tid + r * 256;        // f4 slot 0..511
            int d2 = e >> 5;
            int c4 = (e & 31) * 4;
            int d  = kb * 16 + d2;
            float cc = cs[d];
            float4 va = *(const float4*)&f[(size_t)d * NN + i0 + c4];
            va.x *= cc; va.y *= cc; va.z *= cc; va.w *= cc;
            *(float4*)&As[d2 * 128 + c4] = va;
            *(float4*)&Bs[d2 * 128 + c4] = *(const float4*)&f[(size_t)d * NN + j0 + c4];
        }
        __syncthreads();

        #pragma unroll
        for (int d2 = 0; d2 < 16; ++d2) {
            float a[8], b[8];
            *(float4*)&a[0] = *(float4*)&As[d2 * 128 + ty * 4];
            *(float4*)&a[4] = *(float4*)&As[d2 * 128 + 64 + ty * 4];
            *(float4*)&b[0] = *(float4*)&Bs[d2 * 128 + tx * 4];
            *(float4*)&b[4] = *(float4*)&Bs[d2 * 128 + 64 + tx * 4];
            #pragma unroll
            for (int r = 0; r < 8; ++r)
                #pragma unroll
                for (int c = 0; c < 8; ++c)
                    acc[r][c] = fmaf(a[r], b[c], acc[r][c]);
        }
        __syncthreads();
    }

    // exponentiate (FMA pipe)
    #pragma unroll
    for (int r = 0; r < 8; ++r)
        #pragma unroll
        for (int c = 0; c < 8; ++c)
            acc[r][c] = fexp(acc[r][c]);

    // primary tile store: fp32 + fp16, coalesced
    #pragma unroll
    for (int rr = 0; rr < 8; ++rr) {
        int rowl = ((rr >> 2) * 64) + ty * 4 + (rr & 3);
        size_t rbase = (size_t)(i0 + rowl) * NN + j0;
        #pragma unroll
        for (int cg = 0; cg < 2; ++cg) {
            float4 w = make_float4(acc[rr][cg * 4 + 0], acc[rr][cg * 4 + 1],
                                   acc[rr][cg * 4 + 2], acc[rr][cg * 4 + 3]);
            int coff = cg * 64 + tx * 4;
            *(float4*)&g_S[rbase + coff] = w;
            __half2 h0 = __floats2half2_rn(w.x, w.y);
            __half2 h1 = __floats2half2_rn(w.z, w.w);
            uint2 u = make_uint2(*(unsigned*)&h0, *(unsigned*)&h1);
            *(uint2*)&g_Sh[rbase + coff] = u;
        }
    }

    // mirror tile (ti != tj): stage transposed 32-column chunks through smem
    if (ti != tj) {
        float* st = s_raw;   // st[jl][il] : [32][132]
        #pragma unroll 1
        for (int q = 0; q < 4; ++q) {
            __syncthreads();
            int cg = q >> 1;
            int txlo = (q & 1) * 8;
            if ((tx >> 3) == (q & 1)) {   // participating half of tx range
                #pragma unroll
                for (int rr = 0; rr < 8; ++rr) {
                    int rowl = ((rr >> 2) * 64) + ty * 4 + (rr & 3);
                    int cb = (tx - txlo) * 4;           // 0..28
                    #pragma unroll
                    for (int cc = 0; cc < 4; ++cc)
                        st[(cb + cc) * 132 + rowl] = acc[rr][cg * 4 + cc];
                }
            }
            __syncthreads();
            // write 32 mirror rows (j0+q*32+jl), 128 cols each
            #pragma unroll
            for (int w = 0; w < 4; ++w) {
                int e4 = tid + w * 256;                 // 0..1023
                int jl = e4 >> 5;
                int i4 = (e4 & 31) * 4;
                float4 v = *(float4*)&st[jl * 132 + i4];
                size_t rbase = (size_t)(j0 + q * 32 + jl) * NN + i0;
                *(float4*)&g_S[rbase + i4] = v;
                __half2 h0 = __floats2half2_rn(v.x, v.y);
                __half2 h1 = __floats2half2_rn(v.z, v.w);
                uint2 u = make_uint2(*(unsigned*)&h0, *(unsigned*)&h1);
                *(uint2*)&g_Sh[rbase + i4] = u;
            }
        }
    }
}

// ---------------------------------------------------------------------------
// Kernel 2: per row j: D[j,:] = sum_{k in nbr(j)} Sh[k,:] (fp16 reads, fp32
// accum);  T[j,:] = S[j,:]/D[j,:].  One CTA per j, 512 threads x 8 cols.
// ---------------------------------------------------------------------------
__device__ __forceinline__ void add8(float* acc, uint4 h) {
    float2 p;
    p = __half22float2(*(__half2*)&h.x); acc[0] += p.x; acc[1] += p.y;
    p = __half22float2(*(__half2*)&h.y); acc[2] += p.x; acc[3] += p.y;
    p = __half22float2(*(__half2*)&h.z); acc[4] += p.x; acc[5] += p.y;
    p = __half22float2(*(__half2*)&h.w); acc[6] += p.x; acc[7] += p.y;
}

__global__ void __launch_bounds__(512)
compute_T_kernel() {
    const int j = blockIdx.x;
    __shared__ unsigned short s_idx[MAXNBR];
    __shared__ int s_cnt;
    const int tid = threadIdx.x;

    if (tid == 0) s_cnt = g_cnt[j];
    if (tid < MAXNBR) s_idx[tid] = g_idx[(size_t)j * MAXNBR + tid];
    __syncthreads();
    const int cnt = s_cnt;
    const int c8 = tid * 8;

    float acc[8] = {};
    int k = 0;
    for (; k + 4 <= cnt; k += 4) {
        uint4 h0 = *(const uint4*)&g_Sh[(size_t)s_idx[k + 0] * NN + c8];
        uint4 h1 = *(const uint4*)&g_Sh[(size_t)s_idx[k + 1] * NN + c8];
        uint4 h2 = *(const uint4*)&g_Sh[(size_t)s_idx[k + 2] * NN + c8];
        uint4 h3 = *(const uint4*)&g_Sh[(size_t)s_idx[k + 3] * NN + c8];
        add8(acc, h0); add8(acc, h1); add8(acc, h2); add8(acc, h3);
    }
    for (; k < cnt; ++k) {
        uint4 h = *(const uint4*)&g_Sh[(size_t)s_idx[k] * NN + c8];
        add8(acc, h);
    }

    float4 s0 = *(const float4*)&g_S[(size_t)j * NN + c8];
    float4 s1 = *(const float4*)&g_S[(size_t)j * NN + c8 + 4];
    *(float4*)&g_T[(size_t)j * NN + c8] =
        make_float4(s0.x / acc[0], s0.y / acc[1], s0.z / acc[2], s0.w / acc[3]);
    *(float4*)&g_T[(size_t)j * NN + c8 + 4] =
        make_float4(s1.x / acc[4], s1.y / acc[5], s1.z / acc[6], s1.w / acc[7]);
}

// ---------------------------------------------------------------------------
// Kernel 3: out = T^T.  64x64 tiles, float4 loads/stores, 256 threads.
// ---------------------------------------------------------------------------
__global__ void transpose_kernel(float* __restrict__ out) {
    __shared__ float tile[64][65];
    const int tx = threadIdx.x & 15;       // 16 x float4 = 64 cols
    const int ty = threadIdx.x >> 4;       // 16 rows per step
    const int bx = blockIdx.x, by = blockIdx.y;

    #pragma unroll
    for (int s = 0; s < 4; ++s) {
        int r = s * 16 + ty;
        float4 v = *(const float4*)&g_T[(size_t)(by * 64 + r) * NN + bx * 64 + tx * 4];
        tile[r][tx * 4 + 0] = v.x;
        tile[r][tx * 4 + 1] = v.y;
        tile[r][tx * 4 + 2] = v.z;
        tile[r][tx * 4 + 3] = v.w;
    }
    __syncthreads();
    #pragma unroll
    for (int s = 0; s < 4; ++s) {
        int r = s * 16 + ty;
        float4 w = make_float4(tile[tx * 4 + 0][r], tile[tx * 4 + 1][r],
                               tile[tx * 4 + 2][r], tile[tx * 4 + 3][r]);
        *(float4*)&out[(size_t)(bx * 64 + r) * NN + by * 64 + tx * 4] = w;
    }
}

// ---------------------------------------------------------------------------
extern "C" void kernel_launch(void* const* d_in, const int* in_sizes, int n_in,
                              void* d_out, int out_size) {
    const float* f   = (const float*)d_in[0];   // [128, 4096]
    const float* nbr = (const float*)d_in[1];   // [4096, 4096]
    const float* wq  = (const float*)d_in[2];   // [128]
    const float* wk  = (const float*)d_in[3];   // [128]
    float* out = (float*)d_out;                 // [4096, 4096]

    build_nbr_kernel<<<NN / 8, 256>>>(nbr);
    compute_S_kernel<<<dim3(32, 32), 256>>>(f, wq, wk);
    compute_T_kernel<<<NN, 512>>>();
    transpose_kernel<<<dim3(NN / 64, NN / 64), 256>>>(out);
}